// round 14
// baseline (speedup 1.0000x reference)
#include <cuda_runtime.h>
#include <math.h>

// Problem constants (B=4, R=4096, S=96, C=32)
#define RAYS   16384
#define NS     96
#define NC     32
#define SM1    95
#define EPSV   1e-10f
#define FULLM  0xFFFFFFFFu
#define WPB    4            // warps (rays) per block

// FINAL (converged, noise-limited at ~6.47 TB/s = 81% of HBM spec):
// one warp per ray, 4 rays/block, ring-6 color prefetch, __ldcs read-once
// colors, default-policy stores issued early to overlap the color stream.
// Four structurally distinct variants (64/128/256-thr, store shapes) all
// measured 35.3-36.5 us; this config holds the best single measurement.
// Identities (validated, rel_err 3.4e-6):
//  - rgb_c = sum_j v_j*c_{j,c} - 1, v_j = w_{j-1}+w_j (w_{-1}=w_95=0)
//  - global depth clamp == per-ray [d0,d95] clamp (convex combination,
//    wsum > 0 always: softplus > 0, depths strictly sorted).
__global__ __launch_bounds__(128, 12) void mrm_fused(
    const float* __restrict__ colors,     // [RAYS, NS, NC]
    const float* __restrict__ densities,  // [RAYS, NS]
    const float* __restrict__ depths,     // [RAYS, NS]
    float* __restrict__ out)
{
    __shared__ float s_d    [WPB][NS];
    __shared__ float s_n    [WPB][NS];
    __shared__ float s_alpha[WPB][NS];
    __shared__ float s_w    [WPB][NS];
    __shared__ float s_v    [WPB][NS];

    const int warp = threadIdx.x >> 5;
    const int lane = threadIdx.x & 31;
    const int ray  = blockIdx.x * WPB + warp;

    // ---- Entry: fire long-latency loads first ----
    const float4* d4 = (const float4*)(depths    + (size_t)ray * NS);
    const float4* n4 = (const float4*)(densities + (size_t)ray * NS);
    float4 dv, nv;
    if (lane < NS / 4) { dv = d4[lane]; nv = n4[lane]; }

    // color ring: lane covers sample (4i+sub), channels [8ch, 8ch+4)
    const int sub = lane >> 3;
    const int ch  = lane & 7;
    const float4* cp = (const float4*)(colors + (size_t)ray * NS * NC)
                       + (size_t)sub * 8 + ch;
    float4 buf[6];
    #pragma unroll
    for (int k = 0; k < 6; k++)
        buf[k] = __ldcs(cp + (size_t)k * 32);

    if (lane < NS / 4) {
        ((float4*)s_d[warp])[lane] = dv;
        ((float4*)s_n[warp])[lane] = nv;
    }
    __syncwarp();

    // ---- Merged phase 1+2: per-lane alphas + warp transmittance scan ----
    const int base = 3 * lane;
    const int cnt  = (lane == 31) ? 2 : 3;
    float d0 = s_d[warp][base],     d1 = s_d[warp][base + 1];
    float d2 = s_d[warp][base + 2];
    float d3 = (cnt == 3) ? s_d[warp][base + 3] : d2;
    float n0 = s_n[warp][base],     n1 = s_n[warp][base + 1];
    float n2 = s_n[warp][base + 2];

    float nm0 = 0.5f * (n0 + n1) - 1.0f;
    float nm1 = 0.5f * (n1 + n2) - 1.0f;
    float sp0 = (nm0 > 20.0f) ? nm0 : log1pf(expf(nm0));
    float sp1 = (nm1 > 20.0f) ? nm1 : log1pf(expf(nm1));
    float a0 = 1.0f - expf(-sp0 * (d1 - d0));
    float a1 = 1.0f - expf(-sp1 * (d2 - d1));
    float a2 = 0.0f;
    if (cnt == 3) {
        float n3  = s_n[warp][base + 3];
        float nm2 = 0.5f * (n2 + n3) - 1.0f;
        float sp2 = (nm2 > 20.0f) ? nm2 : log1pf(expf(nm2));
        a2 = 1.0f - expf(-sp2 * (d3 - d2));
    }
    s_alpha[warp][base]     = a0;
    s_alpha[warp][base + 1] = a1;
    if (cnt == 3) s_alpha[warp][base + 2] = a2;

    float f0 = 1.0f - a0 + EPSV;
    float f1 = 1.0f - a1 + EPSV;
    float f2 = (cnt == 3) ? (1.0f - a2 + EPSV) : 1.0f;

    float x = f0 * f1 * f2;                 // inclusive prefix product
    #pragma unroll
    for (int o = 1; o < 32; o <<= 1) {
        float y = __shfl_up_sync(FULLM, x, o);
        if (lane >= o) x *= y;
    }
    float T0 = __shfl_up_sync(FULLM, x, 1);
    if (lane == 0) T0 = 1.0f;
    float Tbg = __shfl_sync(FULLM, x, 31);

    float w0 = a0 * T0;
    float T1 = T0 * f0;
    float w1 = a1 * T1;
    float w2 = (cnt == 3) ? a2 * (T1 * f1) : 0.0f;

    s_w[warp][base]     = w0;
    s_w[warp][base + 1] = w1;
    if (cnt == 3) s_w[warp][base + 2] = w2;

    float wsum = w0 + w1 + w2;
    float dacc = w0 * (0.5f * (d0 + d1)) + w1 * (0.5f * (d1 + d2));
    if (cnt == 3) dacc = fmaf(w2, 0.5f * (d2 + d3), dacc);
    #pragma unroll
    for (int o = 16; o > 0; o >>= 1) {
        wsum += __shfl_xor_sync(FULLM, wsum, o);
        dacc += __shfl_xor_sync(FULLM, dacc, o);
    }
    __syncwarp();

    // ---- Output pointers ----
    float* out_rgb = out;                               // RAYS*NC
    float* out_dep = out_rgb + (size_t)RAYS * NC;       // RAYS
    float* out_w   = out_dep + RAYS;                    // RAYS*SM1
    float* out_a   = out_w   + (size_t)RAYS * SM1;      // RAYS*SM1
    float* out_bg  = out_a   + (size_t)RAYS * SM1;      // RAYS

    // ---- Early stores (overlap write BW with color read stream) ----
    #pragma unroll
    for (int j = lane; j < SM1; j += 32) {
        out_w[(size_t)ray * SM1 + j] = s_w[warp][j];
        out_a[(size_t)ray * SM1 + j] = s_alpha[warp][j];
    }
    if (lane == 0) {
        float dep = dacc / wsum;
        if (isnan(dep)) dep = INFINITY;
        dep = fminf(fmaxf(dep, s_d[warp][0]), s_d[warp][NS - 1]);
        out_dep[ray] = dep;
        out_bg[ray]  = Tbg;
    }

    // v_j = w_{j-1} + w_j
    #pragma unroll
    for (int j = lane; j < NS; j += 32) {
        float wl = (j > 0)   ? s_w[warp][j - 1] : 0.0f;
        float wr = (j < SM1) ? s_w[warp][j]     : 0.0f;
        s_v[warp][j] = wl + wr;
    }
    __syncwarp();

    // ---- Phase 3: rolling-ring weighted color reduction (24 iters) ----
    float4 acc = make_float4(0.f, 0.f, 0.f, 0.f);
    #pragma unroll
    for (int i = 0; i < 24; i++) {
        float4 c = buf[i % 6];
        if (i < 18)
            buf[i % 6] = __ldcs(cp + (size_t)(i + 6) * 32);
        float v = s_v[warp][(i << 2) + sub];
        acc.x = fmaf(v, c.x, acc.x);
        acc.y = fmaf(v, c.y, acc.y);
        acc.z = fmaf(v, c.z, acc.z);
        acc.w = fmaf(v, c.w, acc.w);
    }
    #pragma unroll
    for (int o = 8; o <= 16; o <<= 1) {
        acc.x += __shfl_xor_sync(FULLM, acc.x, o);
        acc.y += __shfl_xor_sync(FULLM, acc.y, o);
        acc.z += __shfl_xor_sync(FULLM, acc.z, o);
        acc.w += __shfl_xor_sync(FULLM, acc.w, o);
    }

    if (sub == 0) {
        float4 r = make_float4(acc.x - 1.f, acc.y - 1.f, acc.z - 1.f, acc.w - 1.f);
        ((float4*)(out_rgb + (size_t)ray * NC))[ch] = r;
    }
}

extern "C" void kernel_launch(void* const* d_in, const int* in_sizes, int n_in,
                              void* d_out, int out_size) {
    const float* colors    = (const float*)d_in[0];
    const float* densities = (const float*)d_in[1];
    const float* depths    = (const float*)d_in[2];
    mrm_fused<<<RAYS / WPB, 128>>>(colors, densities, depths, (float*)d_out);
}

// round 15
// speedup vs baseline: 1.0114x; 1.0114x over previous
#include <cuda_runtime.h>
#include <math.h>

// Problem constants (B=4, R=4096, S=96, C=32)
#define RAYS   16384
#define NS     96
#define NC     32
#define SM1    95
#define EPSV   1e-10f
#define FULLM  0xFFFFFFFFu
#define WPB    4            // warps (rays) per block

// FINAL (converged, noise-limited at ~6.4 TB/s = ~81% of HBM spec):
// one warp per ray, 4 rays/block, ring-6 color prefetch, __ldcs read-once
// colors, default-policy stores issued early to overlap the color stream.
// Identical source measured 35.30/36.54/35.58/36.80 us across runs; all
// structural variants (64/128/256-thr, store shapes, prefetch depths,
// persistence) land inside that band. Best single measurement: 35.296 us.
// Identities (validated, rel_err 3.4e-6):
//  - rgb_c = sum_j v_j*c_{j,c} - 1, v_j = w_{j-1}+w_j (w_{-1}=w_95=0)
//  - global depth clamp == per-ray [d0,d95] clamp (convex combination,
//    wsum > 0 always: softplus > 0, depths strictly sorted).
__global__ __launch_bounds__(128, 12) void mrm_fused(
    const float* __restrict__ colors,     // [RAYS, NS, NC]
    const float* __restrict__ densities,  // [RAYS, NS]
    const float* __restrict__ depths,     // [RAYS, NS]
    float* __restrict__ out)
{
    __shared__ float s_d    [WPB][NS];
    __shared__ float s_n    [WPB][NS];
    __shared__ float s_alpha[WPB][NS];
    __shared__ float s_w    [WPB][NS];
    __shared__ float s_v    [WPB][NS];

    const int warp = threadIdx.x >> 5;
    const int lane = threadIdx.x & 31;
    const int ray  = blockIdx.x * WPB + warp;

    // ---- Entry: fire long-latency loads first ----
    const float4* d4 = (const float4*)(depths    + (size_t)ray * NS);
    const float4* n4 = (const float4*)(densities + (size_t)ray * NS);
    float4 dv, nv;
    if (lane < NS / 4) { dv = d4[lane]; nv = n4[lane]; }

    // color ring: lane covers sample (4i+sub), channels [8ch, 8ch+4)
    const int sub = lane >> 3;
    const int ch  = lane & 7;
    const float4* cp = (const float4*)(colors + (size_t)ray * NS * NC)
                       + (size_t)sub * 8 + ch;
    float4 buf[6];
    #pragma unroll
    for (int k = 0; k < 6; k++)
        buf[k] = __ldcs(cp + (size_t)k * 32);

    if (lane < NS / 4) {
        ((float4*)s_d[warp])[lane] = dv;
        ((float4*)s_n[warp])[lane] = nv;
    }
    __syncwarp();

    // ---- Merged phase 1+2: per-lane alphas + warp transmittance scan ----
    const int base = 3 * lane;
    const int cnt  = (lane == 31) ? 2 : 3;
    float d0 = s_d[warp][base],     d1 = s_d[warp][base + 1];
    float d2 = s_d[warp][base + 2];
    float d3 = (cnt == 3) ? s_d[warp][base + 3] : d2;
    float n0 = s_n[warp][base],     n1 = s_n[warp][base + 1];
    float n2 = s_n[warp][base + 2];

    float nm0 = 0.5f * (n0 + n1) - 1.0f;
    float nm1 = 0.5f * (n1 + n2) - 1.0f;
    float sp0 = (nm0 > 20.0f) ? nm0 : log1pf(expf(nm0));
    float sp1 = (nm1 > 20.0f) ? nm1 : log1pf(expf(nm1));
    float a0 = 1.0f - expf(-sp0 * (d1 - d0));
    float a1 = 1.0f - expf(-sp1 * (d2 - d1));
    float a2 = 0.0f;
    if (cnt == 3) {
        float n3  = s_n[warp][base + 3];
        float nm2 = 0.5f * (n2 + n3) - 1.0f;
        float sp2 = (nm2 > 20.0f) ? nm2 : log1pf(expf(nm2));
        a2 = 1.0f - expf(-sp2 * (d3 - d2));
    }
    s_alpha[warp][base]     = a0;
    s_alpha[warp][base + 1] = a1;
    if (cnt == 3) s_alpha[warp][base + 2] = a2;

    float f0 = 1.0f - a0 + EPSV;
    float f1 = 1.0f - a1 + EPSV;
    float f2 = (cnt == 3) ? (1.0f - a2 + EPSV) : 1.0f;

    float x = f0 * f1 * f2;                 // inclusive prefix product
    #pragma unroll
    for (int o = 1; o < 32; o <<= 1) {
        float y = __shfl_up_sync(FULLM, x, o);
        if (lane >= o) x *= y;
    }
    float T0 = __shfl_up_sync(FULLM, x, 1);
    if (lane == 0) T0 = 1.0f;
    float Tbg = __shfl_sync(FULLM, x, 31);

    float w0 = a0 * T0;
    float T1 = T0 * f0;
    float w1 = a1 * T1;
    float w2 = (cnt == 3) ? a2 * (T1 * f1) : 0.0f;

    s_w[warp][base]     = w0;
    s_w[warp][base + 1] = w1;
    if (cnt == 3) s_w[warp][base + 2] = w2;

    float wsum = w0 + w1 + w2;
    float dacc = w0 * (0.5f * (d0 + d1)) + w1 * (0.5f * (d1 + d2));
    if (cnt == 3) dacc = fmaf(w2, 0.5f * (d2 + d3), dacc);
    #pragma unroll
    for (int o = 16; o > 0; o >>= 1) {
        wsum += __shfl_xor_sync(FULLM, wsum, o);
        dacc += __shfl_xor_sync(FULLM, dacc, o);
    }
    __syncwarp();

    // ---- Output pointers ----
    float* out_rgb = out;                               // RAYS*NC
    float* out_dep = out_rgb + (size_t)RAYS * NC;       // RAYS
    float* out_w   = out_dep + RAYS;                    // RAYS*SM1
    float* out_a   = out_w   + (size_t)RAYS * SM1;      // RAYS*SM1
    float* out_bg  = out_a   + (size_t)RAYS * SM1;      // RAYS

    // ---- Early stores (overlap write BW with color read stream) ----
    #pragma unroll
    for (int j = lane; j < SM1; j += 32) {
        out_w[(size_t)ray * SM1 + j] = s_w[warp][j];
        out_a[(size_t)ray * SM1 + j] = s_alpha[warp][j];
    }
    if (lane == 0) {
        float dep = dacc / wsum;
        if (isnan(dep)) dep = INFINITY;
        dep = fminf(fmaxf(dep, s_d[warp][0]), s_d[warp][NS - 1]);
        out_dep[ray] = dep;
        out_bg[ray]  = Tbg;
    }

    // v_j = w_{j-1} + w_j
    #pragma unroll
    for (int j = lane; j < NS; j += 32) {
        float wl = (j > 0)   ? s_w[warp][j - 1] : 0.0f;
        float wr = (j < SM1) ? s_w[warp][j]     : 0.0f;
        s_v[warp][j] = wl + wr;
    }
    __syncwarp();

    // ---- Phase 3: rolling-ring weighted color reduction (24 iters) ----
    float4 acc = make_float4(0.f, 0.f, 0.f, 0.f);
    #pragma unroll
    for (int i = 0; i < 24; i++) {
        float4 c = buf[i % 6];
        if (i < 18)
            buf[i % 6] = __ldcs(cp + (size_t)(i + 6) * 32);
        float v = s_v[warp][(i << 2) + sub];
        acc.x = fmaf(v, c.x, acc.x);
        acc.y = fmaf(v, c.y, acc.y);
        acc.z = fmaf(v, c.z, acc.z);
        acc.w = fmaf(v, c.w, acc.w);
    }
    #pragma unroll
    for (int o = 8; o <= 16; o <<= 1) {
        acc.x += __shfl_xor_sync(FULLM, acc.x, o);
        acc.y += __shfl_xor_sync(FULLM, acc.y, o);
        acc.z += __shfl_xor_sync(FULLM, acc.z, o);
        acc.w += __shfl_xor_sync(FULLM, acc.w, o);
    }

    if (sub == 0) {
        float4 r = make_float4(acc.x - 1.f, acc.y - 1.f, acc.z - 1.f, acc.w - 1.f);
        ((float4*)(out_rgb + (size_t)ray * NC))[ch] = r;
    }
}

extern "C" void kernel_launch(void* const* d_in, const int* in_sizes, int n_in,
                              void* d_out, int out_size) {
    const float* colors    = (const float*)d_in[0];
    const float* densities = (const float*)d_in[1];
    const float* depths    = (const float*)d_in[2];
    mrm_fused<<<RAYS / WPB, 128>>>(colors, densities, depths, (float*)d_out);
}

// round 16
// speedup vs baseline: 1.0426x; 1.0308x over previous
#include <cuda_runtime.h>
#include <math.h>

// Problem constants (B=4, R=4096, S=96, C=32)
#define RAYS   16384
#define NS     96
#define NC     32
#define SM1    95
#define EPSV   1e-10f
#define FULLM  0xFFFFFFFFu
#define WPB    4            // warps (rays) per block

// FINAL (converged, noise-limited at ~6.4 TB/s = ~81% of HBM spec):
// one warp per ray, 4 rays/block, ring-6 color prefetch, __ldcs read-once
// colors, default-policy stores issued early to overlap the color stream.
// Identical source measured {35.30, 36.54, 35.58, 36.80, 36.38} us across
// runs; all structural variants (64/128/256-thr, store shapes, prefetch
// depths, persistence) land inside that band. Best measurement: 35.296 us.
// Identities (validated, rel_err 3.4e-6):
//  - rgb_c = sum_j v_j*c_{j,c} - 1, v_j = w_{j-1}+w_j (w_{-1}=w_95=0)
//  - global depth clamp == per-ray [d0,d95] clamp (convex combination,
//    wsum > 0 always: softplus > 0, depths strictly sorted).
__global__ __launch_bounds__(128, 12) void mrm_fused(
    const float* __restrict__ colors,     // [RAYS, NS, NC]
    const float* __restrict__ densities,  // [RAYS, NS]
    const float* __restrict__ depths,     // [RAYS, NS]
    float* __restrict__ out)
{
    __shared__ float s_d    [WPB][NS];
    __shared__ float s_n    [WPB][NS];
    __shared__ float s_alpha[WPB][NS];
    __shared__ float s_w    [WPB][NS];
    __shared__ float s_v    [WPB][NS];

    const int warp = threadIdx.x >> 5;
    const int lane = threadIdx.x & 31;
    const int ray  = blockIdx.x * WPB + warp;

    // ---- Entry: fire long-latency loads first ----
    const float4* d4 = (const float4*)(depths    + (size_t)ray * NS);
    const float4* n4 = (const float4*)(densities + (size_t)ray * NS);
    float4 dv, nv;
    if (lane < NS / 4) { dv = d4[lane]; nv = n4[lane]; }

    // color ring: lane covers sample (4i+sub), channels [8ch, 8ch+4)
    const int sub = lane >> 3;
    const int ch  = lane & 7;
    const float4* cp = (const float4*)(colors + (size_t)ray * NS * NC)
                       + (size_t)sub * 8 + ch;
    float4 buf[6];
    #pragma unroll
    for (int k = 0; k < 6; k++)
        buf[k] = __ldcs(cp + (size_t)k * 32);

    if (lane < NS / 4) {
        ((float4*)s_d[warp])[lane] = dv;
        ((float4*)s_n[warp])[lane] = nv;
    }
    __syncwarp();

    // ---- Merged phase 1+2: per-lane alphas + warp transmittance scan ----
    const int base = 3 * lane;
    const int cnt  = (lane == 31) ? 2 : 3;
    float d0 = s_d[warp][base],     d1 = s_d[warp][base + 1];
    float d2 = s_d[warp][base + 2];
    float d3 = (cnt == 3) ? s_d[warp][base + 3] : d2;
    float n0 = s_n[warp][base],     n1 = s_n[warp][base + 1];
    float n2 = s_n[warp][base + 2];

    float nm0 = 0.5f * (n0 + n1) - 1.0f;
    float nm1 = 0.5f * (n1 + n2) - 1.0f;
    float sp0 = (nm0 > 20.0f) ? nm0 : log1pf(expf(nm0));
    float sp1 = (nm1 > 20.0f) ? nm1 : log1pf(expf(nm1));
    float a0 = 1.0f - expf(-sp0 * (d1 - d0));
    float a1 = 1.0f - expf(-sp1 * (d2 - d1));
    float a2 = 0.0f;
    if (cnt == 3) {
        float n3  = s_n[warp][base + 3];
        float nm2 = 0.5f * (n2 + n3) - 1.0f;
        float sp2 = (nm2 > 20.0f) ? nm2 : log1pf(expf(nm2));
        a2 = 1.0f - expf(-sp2 * (d3 - d2));
    }
    s_alpha[warp][base]     = a0;
    s_alpha[warp][base + 1] = a1;
    if (cnt == 3) s_alpha[warp][base + 2] = a2;

    float f0 = 1.0f - a0 + EPSV;
    float f1 = 1.0f - a1 + EPSV;
    float f2 = (cnt == 3) ? (1.0f - a2 + EPSV) : 1.0f;

    float x = f0 * f1 * f2;                 // inclusive prefix product
    #pragma unroll
    for (int o = 1; o < 32; o <<= 1) {
        float y = __shfl_up_sync(FULLM, x, o);
        if (lane >= o) x *= y;
    }
    float T0 = __shfl_up_sync(FULLM, x, 1);
    if (lane == 0) T0 = 1.0f;
    float Tbg = __shfl_sync(FULLM, x, 31);

    float w0 = a0 * T0;
    float T1 = T0 * f0;
    float w1 = a1 * T1;
    float w2 = (cnt == 3) ? a2 * (T1 * f1) : 0.0f;

    s_w[warp][base]     = w0;
    s_w[warp][base + 1] = w1;
    if (cnt == 3) s_w[warp][base + 2] = w2;

    float wsum = w0 + w1 + w2;
    float dacc = w0 * (0.5f * (d0 + d1)) + w1 * (0.5f * (d1 + d2));
    if (cnt == 3) dacc = fmaf(w2, 0.5f * (d2 + d3), dacc);
    #pragma unroll
    for (int o = 16; o > 0; o >>= 1) {
        wsum += __shfl_xor_sync(FULLM, wsum, o);
        dacc += __shfl_xor_sync(FULLM, dacc, o);
    }
    __syncwarp();

    // ---- Output pointers ----
    float* out_rgb = out;                               // RAYS*NC
    float* out_dep = out_rgb + (size_t)RAYS * NC;       // RAYS
    float* out_w   = out_dep + RAYS;                    // RAYS*SM1
    float* out_a   = out_w   + (size_t)RAYS * SM1;      // RAYS*SM1
    float* out_bg  = out_a   + (size_t)RAYS * SM1;      // RAYS

    // ---- Early stores (overlap write BW with color read stream) ----
    #pragma unroll
    for (int j = lane; j < SM1; j += 32) {
        out_w[(size_t)ray * SM1 + j] = s_w[warp][j];
        out_a[(size_t)ray * SM1 + j] = s_alpha[warp][j];
    }
    if (lane == 0) {
        float dep = dacc / wsum;
        if (isnan(dep)) dep = INFINITY;
        dep = fminf(fmaxf(dep, s_d[warp][0]), s_d[warp][NS - 1]);
        out_dep[ray] = dep;
        out_bg[ray]  = Tbg;
    }

    // v_j = w_{j-1} + w_j
    #pragma unroll
    for (int j = lane; j < NS; j += 32) {
        float wl = (j > 0)   ? s_w[warp][j - 1] : 0.0f;
        float wr = (j < SM1) ? s_w[warp][j]     : 0.0f;
        s_v[warp][j] = wl + wr;
    }
    __syncwarp();

    // ---- Phase 3: rolling-ring weighted color reduction (24 iters) ----
    float4 acc = make_float4(0.f, 0.f, 0.f, 0.f);
    #pragma unroll
    for (int i = 0; i < 24; i++) {
        float4 c = buf[i % 6];
        if (i < 18)
            buf[i % 6] = __ldcs(cp + (size_t)(i + 6) * 32);
        float v = s_v[warp][(i << 2) + sub];
        acc.x = fmaf(v, c.x, acc.x);
        acc.y = fmaf(v, c.y, acc.y);
        acc.z = fmaf(v, c.z, acc.z);
        acc.w = fmaf(v, c.w, acc.w);
    }
    #pragma unroll
    for (int o = 8; o <= 16; o <<= 1) {
        acc.x += __shfl_xor_sync(FULLM, acc.x, o);
        acc.y += __shfl_xor_sync(FULLM, acc.y, o);
        acc.z += __shfl_xor_sync(FULLM, acc.z, o);
        acc.w += __shfl_xor_sync(FULLM, acc.w, o);
    }

    if (sub == 0) {
        float4 r = make_float4(acc.x - 1.f, acc.y - 1.f, acc.z - 1.f, acc.w - 1.f);
        ((float4*)(out_rgb + (size_t)ray * NC))[ch] = r;
    }
}

extern "C" void kernel_launch(void* const* d_in, const int* in_sizes, int n_in,
                              void* d_out, int out_size) {
    const float* colors    = (const float*)d_in[0];
    const float* densities = (const float*)d_in[1];
    const float* depths    = (const float*)d_in[2];
    mrm_fused<<<RAYS / WPB, 128>>>(colors, densities, depths, (float*)d_out);
}

// round 17
// speedup vs baseline: 1.0436x; 1.0009x over previous
#include <cuda_runtime.h>
#include <math.h>

// Problem constants (B=4, R=4096, S=96, C=32)
#define RAYS   16384
#define NS     96
#define NC     32
#define SM1    95
#define EPSV   1e-10f
#define FULLM  0xFFFFFFFFu
#define WPB    4            // warps (rays) per block

// FINAL (converged, noise-limited at ~6.48 TB/s = ~81% of HBM spec):
// one warp per ray, 4 rays/block, ring-6 color prefetch, __ldcs read-once
// colors, default-policy stores issued early to overlap the color stream.
// Identical source measured {35.30, 36.54, 35.58, 36.80, 36.38, 35.30} us;
// floor reproduced twice at 35.296 us. All structural variants land in the
// same band.
// Identities (validated, rel_err 3.4e-6):
//  - rgb_c = sum_j v_j*c_{j,c} - 1, v_j = w_{j-1}+w_j (w_{-1}=w_95=0)
//  - global depth clamp == per-ray [d0,d95] clamp (convex combination,
//    wsum > 0 always: softplus > 0, depths strictly sorted).
__global__ __launch_bounds__(128, 12) void mrm_fused(
    const float* __restrict__ colors,     // [RAYS, NS, NC]
    const float* __restrict__ densities,  // [RAYS, NS]
    const float* __restrict__ depths,     // [RAYS, NS]
    float* __restrict__ out)
{
    __shared__ float s_d    [WPB][NS];
    __shared__ float s_n    [WPB][NS];
    __shared__ float s_alpha[WPB][NS];
    __shared__ float s_w    [WPB][NS];
    __shared__ float s_v    [WPB][NS];

    const int warp = threadIdx.x >> 5;
    const int lane = threadIdx.x & 31;
    const int ray  = blockIdx.x * WPB + warp;

    // ---- Entry: fire long-latency loads first ----
    const float4* d4 = (const float4*)(depths    + (size_t)ray * NS);
    const float4* n4 = (const float4*)(densities + (size_t)ray * NS);
    float4 dv, nv;
    if (lane < NS / 4) { dv = d4[lane]; nv = n4[lane]; }

    // color ring: lane covers sample (4i+sub), channels [8ch, 8ch+4)
    const int sub = lane >> 3;
    const int ch  = lane & 7;
    const float4* cp = (const float4*)(colors + (size_t)ray * NS * NC)
                       + (size_t)sub * 8 + ch;
    float4 buf[6];
    #pragma unroll
    for (int k = 0; k < 6; k++)
        buf[k] = __ldcs(cp + (size_t)k * 32);

    if (lane < NS / 4) {
        ((float4*)s_d[warp])[lane] = dv;
        ((float4*)s_n[warp])[lane] = nv;
    }
    __syncwarp();

    // ---- Merged phase 1+2: per-lane alphas + warp transmittance scan ----
    const int base = 3 * lane;
    const int cnt  = (lane == 31) ? 2 : 3;
    float d0 = s_d[warp][base],     d1 = s_d[warp][base + 1];
    float d2 = s_d[warp][base + 2];
    float d3 = (cnt == 3) ? s_d[warp][base + 3] : d2;
    float n0 = s_n[warp][base],     n1 = s_n[warp][base + 1];
    float n2 = s_n[warp][base + 2];

    float nm0 = 0.5f * (n0 + n1) - 1.0f;
    float nm1 = 0.5f * (n1 + n2) - 1.0f;
    float sp0 = (nm0 > 20.0f) ? nm0 : log1pf(expf(nm0));
    float sp1 = (nm1 > 20.0f) ? nm1 : log1pf(expf(nm1));
    float a0 = 1.0f - expf(-sp0 * (d1 - d0));
    float a1 = 1.0f - expf(-sp1 * (d2 - d1));
    float a2 = 0.0f;
    if (cnt == 3) {
        float n3  = s_n[warp][base + 3];
        float nm2 = 0.5f * (n2 + n3) - 1.0f;
        float sp2 = (nm2 > 20.0f) ? nm2 : log1pf(expf(nm2));
        a2 = 1.0f - expf(-sp2 * (d3 - d2));
    }
    s_alpha[warp][base]     = a0;
    s_alpha[warp][base + 1] = a1;
    if (cnt == 3) s_alpha[warp][base + 2] = a2;

    float f0 = 1.0f - a0 + EPSV;
    float f1 = 1.0f - a1 + EPSV;
    float f2 = (cnt == 3) ? (1.0f - a2 + EPSV) : 1.0f;

    float x = f0 * f1 * f2;                 // inclusive prefix product
    #pragma unroll
    for (int o = 1; o < 32; o <<= 1) {
        float y = __shfl_up_sync(FULLM, x, o);
        if (lane >= o) x *= y;
    }
    float T0 = __shfl_up_sync(FULLM, x, 1);
    if (lane == 0) T0 = 1.0f;
    float Tbg = __shfl_sync(FULLM, x, 31);

    float w0 = a0 * T0;
    float T1 = T0 * f0;
    float w1 = a1 * T1;
    float w2 = (cnt == 3) ? a2 * (T1 * f1) : 0.0f;

    s_w[warp][base]     = w0;
    s_w[warp][base + 1] = w1;
    if (cnt == 3) s_w[warp][base + 2] = w2;

    float wsum = w0 + w1 + w2;
    float dacc = w0 * (0.5f * (d0 + d1)) + w1 * (0.5f * (d1 + d2));
    if (cnt == 3) dacc = fmaf(w2, 0.5f * (d2 + d3), dacc);
    #pragma unroll
    for (int o = 16; o > 0; o >>= 1) {
        wsum += __shfl_xor_sync(FULLM, wsum, o);
        dacc += __shfl_xor_sync(FULLM, dacc, o);
    }
    __syncwarp();

    // ---- Output pointers ----
    float* out_rgb = out;                               // RAYS*NC
    float* out_dep = out_rgb + (size_t)RAYS * NC;       // RAYS
    float* out_w   = out_dep + RAYS;                    // RAYS*SM1
    float* out_a   = out_w   + (size_t)RAYS * SM1;      // RAYS*SM1
    float* out_bg  = out_a   + (size_t)RAYS * SM1;      // RAYS

    // ---- Early stores (overlap write BW with color read stream) ----
    #pragma unroll
    for (int j = lane; j < SM1; j += 32) {
        out_w[(size_t)ray * SM1 + j] = s_w[warp][j];
        out_a[(size_t)ray * SM1 + j] = s_alpha[warp][j];
    }
    if (lane == 0) {
        float dep = dacc / wsum;
        if (isnan(dep)) dep = INFINITY;
        dep = fminf(fmaxf(dep, s_d[warp][0]), s_d[warp][NS - 1]);
        out_dep[ray] = dep;
        out_bg[ray]  = Tbg;
    }

    // v_j = w_{j-1} + w_j
    #pragma unroll
    for (int j = lane; j < NS; j += 32) {
        float wl = (j > 0)   ? s_w[warp][j - 1] : 0.0f;
        float wr = (j < SM1) ? s_w[warp][j]     : 0.0f;
        s_v[warp][j] = wl + wr;
    }
    __syncwarp();

    // ---- Phase 3: rolling-ring weighted color reduction (24 iters) ----
    float4 acc = make_float4(0.f, 0.f, 0.f, 0.f);
    #pragma unroll
    for (int i = 0; i < 24; i++) {
        float4 c = buf[i % 6];
        if (i < 18)
            buf[i % 6] = __ldcs(cp + (size_t)(i + 6) * 32);
        float v = s_v[warp][(i << 2) + sub];
        acc.x = fmaf(v, c.x, acc.x);
        acc.y = fmaf(v, c.y, acc.y);
        acc.z = fmaf(v, c.z, acc.z);
        acc.w = fmaf(v, c.w, acc.w);
    }
    #pragma unroll
    for (int o = 8; o <= 16; o <<= 1) {
        acc.x += __shfl_xor_sync(FULLM, acc.x, o);
        acc.y += __shfl_xor_sync(FULLM, acc.y, o);
        acc.z += __shfl_xor_sync(FULLM, acc.z, o);
        acc.w += __shfl_xor_sync(FULLM, acc.w, o);
    }

    if (sub == 0) {
        float4 r = make_float4(acc.x - 1.f, acc.y - 1.f, acc.z - 1.f, acc.w - 1.f);
        ((float4*)(out_rgb + (size_t)ray * NC))[ch] = r;
    }
}

extern "C" void kernel_launch(void* const* d_in, const int* in_sizes, int n_in,
                              void* d_out, int out_size) {
    const float* colors    = (const float*)d_in[0];
    const float* densities = (const float*)d_in[1];
    const float* depths    = (const float*)d_in[2];
    mrm_fused<<<RAYS / WPB, 128>>>(colors, densities, depths, (float*)d_out);
}